// round 3
// baseline (speedup 1.0000x reference)
#include <cuda_runtime.h>
#include <math.h>

#define Bc   2
#define Nc   2048
#define Hc   8
#define DHc  32
#define Ec   65536
#define DIN  256
#define Oc   256

// ---------------- scratch globals (no allocation allowed) ----------------
__device__ float g_Q [Bc*Hc*Nc*DHc];   // [b][h][n][d]
__device__ float g_Kt[Bc*Hc*DHc*Nc];   // [b][h][d][n]  (transposed K)
__device__ float g_V [Bc*Hc*Nc*DHc];   // [b][h][n][d]
__device__ float g_ea[(long)Bc*Ec*Hc]; // ffn(ffn(edge_attr)) [b][e][h]
__device__ int   g_cnt   [Bc*Nc];
__device__ int   g_rowptr[Bc*Nc+1];
__device__ int   g_fill  [Bc*Nc];
__device__ int   g_colv  [Bc*Ec];
__device__ float g_eav   [(long)Bc*Ec*Hc];

// ---------------- K1: QKV projection GEMM -------------------------------
// out[m][cc] = x[m]@qkv_w[:,cc] + b[cc]; m = b*N+n, cc in [0,768)
__global__ void qkv_kernel(const float* __restrict__ x,
                           const float* __restrict__ w,
                           const float* __restrict__ bias) {
    __shared__ __align__(16) float As[16][64];   // [k][m]
    __shared__ __align__(16) float Bs[16][64];   // [k][c]
    int tx = threadIdx.x, ty = threadIdx.y;      // 16x16
    int tid = ty * 16 + tx;
    int mb = blockIdx.y * 64, cb = blockIdx.x * 64;

    float acc[4][4];
#pragma unroll
    for (int i = 0; i < 4; i++)
#pragma unroll
        for (int j = 0; j < 4; j++) acc[i][j] = 0.f;

    for (int kb = 0; kb < DIN; kb += 16) {
        {   // load x tile (transposed store)
            int m = tid >> 2, k4 = (tid & 3) * 4;
            float4 f = *(const float4*)&x[(long)(mb + m) * DIN + kb + k4];
            As[k4 + 0][m] = f.x; As[k4 + 1][m] = f.y;
            As[k4 + 2][m] = f.z; As[k4 + 3][m] = f.w;
        }
        {   // load w tile
            int k = tid >> 4, c4 = (tid & 15) * 4;
            *(float4*)&Bs[k][c4] = *(const float4*)&w[(long)(kb + k) * 768 + cb + c4];
        }
        __syncthreads();
#pragma unroll
        for (int kk = 0; kk < 16; kk++) {
            float4 ra = *(const float4*)&As[kk][ty * 4];
            float4 rb = *(const float4*)&Bs[kk][tx * 4];
            float a[4] = {ra.x, ra.y, ra.z, ra.w};
            float b4[4] = {rb.x, rb.y, rb.z, rb.w};
#pragma unroll
            for (int i = 0; i < 4; i++)
#pragma unroll
                for (int j = 0; j < 4; j++) acc[i][j] += a[i] * b4[j];
        }
        __syncthreads();
    }
    // scatter to Q / Kt / V layouts
#pragma unroll
    for (int i = 0; i < 4; i++) {
        int m = mb + ty * 4 + i;
        int b = m >> 11, n = m & (Nc - 1);
#pragma unroll
        for (int j = 0; j < 4; j++) {
            int cc = cb + tx * 4 + j;
            int sel = cc / Oc, r = cc % Oc;
            int h = r / DHc, d = r % DHc;
            float val = acc[i][j] + bias[cc];
            if (sel == 0)      g_Q [((b*Hc + h)*Nc + n)*DHc + d] = val;
            else if (sel == 1) g_Kt[((b*Hc + h)*DHc + d)*Nc + n] = val;
            else               g_V [((b*Hc + h)*Nc + n)*DHc + d] = val;
        }
    }
}

// ---------------- K2: edge FFN (applied twice) ---------------------------
__global__ void edge_ffn_kernel(const float* __restrict__ ea,
                                const float* __restrict__ w1, const float* __restrict__ b1,
                                const float* __restrict__ w2, const float* __restrict__ b2) {
    __shared__ float sw1[64], sw2[64], sb1[8], sb2[8];
    int t = threadIdx.x;
    if (t < 64) { sw1[t] = w1[t]; sw2[t] = w2[t]; }
    if (t < 8)  { sb1[t] = b1[t]; sb2[t] = b2[t]; }
    __syncthreads();

    long idx = (long)blockIdx.x * 256 + t;   // over B*E
    float v[8], u[8];
    const float4* p = (const float4*)(ea + idx * 8);
    float4 f0 = p[0], f1 = p[1];
    v[0]=f0.x; v[1]=f0.y; v[2]=f0.z; v[3]=f0.w;
    v[4]=f1.x; v[5]=f1.y; v[6]=f1.z; v[7]=f1.w;

#pragma unroll
    for (int rep = 0; rep < 2; rep++) {
#pragma unroll
        for (int j = 0; j < 8; j++) {
            float a = sb1[j];
#pragma unroll
            for (int i = 0; i < 8; i++) a += v[i] * sw1[i * 8 + j];
            u[j] = fmaxf(a, 0.f);
        }
#pragma unroll
        for (int j = 0; j < 8; j++) {
            float a = sb2[j];
#pragma unroll
            for (int i = 0; i < 8; i++) a += u[i] * sw2[i * 8 + j];
            v[j] = a;
        }
    }
    float4 o0 = {v[0], v[1], v[2], v[3]}, o1 = {v[4], v[5], v[6], v[7]};
    float4* q = (float4*)(g_ea + idx * 8);
    q[0] = o0; q[1] = o1;
}

// ---------------- K3: CSR build ------------------------------------------
__global__ void zero_cnt_kernel() {
    int i = blockIdx.x * 256 + threadIdx.x;
    if (i < Bc * Nc) g_cnt[i] = 0;
}
__global__ void count_kernel(const int* __restrict__ ei) {
    int idx = blockIdx.x * 256 + threadIdx.x;   // over B*E
    int b = idx / Ec, e = idx - b * Ec;
    int u = ei[(long)b * 2 * Ec + e];
    atomicAdd(&g_cnt[b * Nc + u], 1);
}
__global__ void scan_kernel() {
    __shared__ int part[1024];
    int t = threadIdx.x;
    int l0 = g_cnt[t*4], l1 = g_cnt[t*4+1], l2 = g_cnt[t*4+2], l3 = g_cnt[t*4+3];
    int sum = l0 + l1 + l2 + l3;
    part[t] = sum;
    __syncthreads();
    for (int off = 1; off < 1024; off <<= 1) {
        int v = (t >= off) ? part[t - off] : 0;
        __syncthreads();
        part[t] += v;
        __syncthreads();
    }
    int run = part[t] - sum;   // exclusive base
    g_rowptr[t*4]   = run; g_fill[t*4]   = run; run += l0;
    g_rowptr[t*4+1] = run; g_fill[t*4+1] = run; run += l1;
    g_rowptr[t*4+2] = run; g_fill[t*4+2] = run; run += l2;
    g_rowptr[t*4+3] = run; g_fill[t*4+3] = run; run += l3;
    if (t == 1023) g_rowptr[Bc * Nc] = run;
}
__global__ void scatter_kernel(const int* __restrict__ ei) {
    int idx = blockIdx.x * 256 + threadIdx.x;   // over B*E
    int b = idx / Ec, e = idx - b * Ec;
    int u = ei[(long)b * 2 * Ec + e];
    int v = ei[(long)b * 2 * Ec + Ec + e];
    int pos = atomicAdd(&g_fill[b * Nc + u], 1);
    g_colv[pos] = v;
    const float4* src = (const float4*)(g_ea + (long)idx * 8);
    float4* dst = (float4*)(g_eav + (long)pos * 8);
    dst[0] = src[0]; dst[1] = src[1];
}

// ---------------- K4: attention, one block per (b,q), all 8 heads --------
__global__ void __launch_bounds__(256) attn_kernel(
        const float* __restrict__ adj,
        const float* __restrict__ shifts, const float* __restrict__ widths,
        const float* __restrict__ selfw, float* __restrict__ out) {
    extern __shared__ __align__(16) float sm[];
    float* s      = sm;                 // 8 * 2048
    float* adjrow = sm + 8 * Nc;        // 2048
    float* qsm    = adjrow + Nc;        // 256

    int tid  = threadIdx.x;
    int lane = tid & 31, h = tid >> 5;  // warp <-> head
    int bq = blockIdx.x;
    int b  = bq >> 11, q = bq & (Nc - 1);

    // stage q vectors and adj row
    qsm[tid] = g_Q[((b*Hc + h)*Nc + q)*DHc + lane];
    {
        const float4* arow = (const float4*)(adj + (long)bq * Nc);
        float4* adst = (float4*)adjrow;
        for (int i = tid; i < Nc / 4; i += 256) adst[i] = arow[i];
    }
    __syncthreads();

    float ql[32];
#pragma unroll
    for (int d = 0; d < 32; d++) ql[d] = qsm[h * 32 + d];
    float sh = shifts[h], wd = widths[h], sw = selfw[h];
    float inv2w2 = 1.0f / (2.0f * wd * wd);
    const float LOGMIN   = -13.815510557964274f;   // log(1e-6)
    const float INVSCALE = 0.17677669529663687f;   // 1/sqrt(32)

    // --- QK^T + moire + self-loop ---
    const float4* Kt4 = (const float4*)(g_Kt + (long)((b*Hc + h)*DHc) * Nc);
    float* srow = s + h * Nc;
    for (int j = 0; j < 16; j++) {
        int k = j * 128 + lane * 4;
        float4 acc = {0.f, 0.f, 0.f, 0.f};
#pragma unroll
        for (int d = 0; d < 32; d++) {
            float4 f = Kt4[d * (Nc / 4) + (k >> 2)];
            acc.x += ql[d] * f.x; acc.y += ql[d] * f.y;
            acc.z += ql[d] * f.z; acc.w += ql[d] * f.w;
        }
        float4 a4 = *(const float4*)&adjrow[k];
        float4 r;
        { float dd = a4.x - sh; r.x = acc.x * INVSCALE + fmaxf(-dd*dd*inv2w2, LOGMIN); }
        { float dd = a4.y - sh; r.y = acc.y * INVSCALE + fmaxf(-dd*dd*inv2w2, LOGMIN); }
        { float dd = a4.z - sh; r.z = acc.z * INVSCALE + fmaxf(-dd*dd*inv2w2, LOGMIN); }
        { float dd = a4.w - sh; r.w = acc.w * INVSCALE + fmaxf(-dd*dd*inv2w2, LOGMIN); }
        if (q >= k && q < k + 4) ((float*)&r)[q - k] += sw;
        *(float4*)&srow[k] = r;
    }
    __syncthreads();

    // --- edge bias scatter (unique (u,v) per batch -> race-free) ---
    int r0 = g_rowptr[bq], r1 = g_rowptr[bq + 1];
    for (int idx = r0 + tid; idx < r1; idx += 256) {
        int v = g_colv[idx];
        const float* ev = g_eav + (long)idx * 8;
#pragma unroll
        for (int hh = 0; hh < 8; hh++) s[hh * Nc + v] += ev[hh];
    }
    __syncthreads();

    // --- softmax (per head warp) ---
    float m = -1e30f;
    for (int j = 0; j < 16; j++) {
        float4 v4 = *(const float4*)&srow[j * 128 + lane * 4];
        m = fmaxf(m, fmaxf(fmaxf(v4.x, v4.y), fmaxf(v4.z, v4.w)));
    }
#pragma unroll
    for (int o = 16; o; o >>= 1) m = fmaxf(m, __shfl_xor_sync(~0u, m, o));
    float l = 0.f;
    for (int j = 0; j < 16; j++) {
        float4 v4 = *(const float4*)&srow[j * 128 + lane * 4];
        v4.x = __expf(v4.x - m); v4.y = __expf(v4.y - m);
        v4.z = __expf(v4.z - m); v4.w = __expf(v4.w - m);
        l += v4.x + v4.y + v4.z + v4.w;
        *(float4*)&srow[j * 128 + lane * 4] = v4;
    }
#pragma unroll
    for (int o = 16; o; o >>= 1) l += __shfl_xor_sync(~0u, l, o);

    // --- P @ V ---
    const float4* V4 = (const float4*)(g_V + (long)((b*Hc + h)*Nc) * DHc);
    int dgi = lane & 7, kg = lane >> 3;
    float4 acc = {0.f, 0.f, 0.f, 0.f};
    for (int it = 0; it < Nc / 4; it++) {
        int k = it * 4 + kg;
        float p = srow[k];
        float4 f = V4[k * 8 + dgi];
        acc.x += p * f.x; acc.y += p * f.y;
        acc.z += p * f.z; acc.w += p * f.w;
    }
#pragma unroll
    for (int o = 8; o < 32; o <<= 1) {
        acc.x += __shfl_xor_sync(~0u, acc.x, o);
        acc.y += __shfl_xor_sync(~0u, acc.y, o);
        acc.z += __shfl_xor_sync(~0u, acc.z, o);
        acc.w += __shfl_xor_sync(~0u, acc.w, o);
    }
    if (lane < 8) {
        float invl = 1.0f / l;
        float4 o4 = {acc.x * invl, acc.y * invl, acc.z * invl, acc.w * invl};
        *(float4*)&out[(long)bq * Oc + h * 32 + lane * 4] = o4;
    }
}

// ---------------- launch --------------------------------------------------
extern "C" void kernel_launch(void* const* d_in, const int* in_sizes, int n_in,
                              void* d_out, int out_size) {
    const float* x        = (const float*)d_in[0];
    const float* adj      = (const float*)d_in[1];
    const float* edge_attr= (const float*)d_in[2];
    const float* qkv_w    = (const float*)d_in[3];
    const float* qkv_b    = (const float*)d_in[4];
    const float* e_w1     = (const float*)d_in[5];
    const float* e_b1     = (const float*)d_in[6];
    const float* e_w2     = (const float*)d_in[7];
    const float* e_b2     = (const float*)d_in[8];
    const float* shifts   = (const float*)d_in[9];
    const float* widths   = (const float*)d_in[10];
    const float* selfw    = (const float*)d_in[11];
    const int*   ei       = (const int*)d_in[12];
    float* out = (float*)d_out;

    qkv_kernel<<<dim3(12, 64), dim3(16, 16)>>>(x, qkv_w, qkv_b);
    edge_ffn_kernel<<<(Bc * Ec) / 256, 256>>>(edge_attr, e_w1, e_b1, e_w2, e_b2);
    zero_cnt_kernel<<<(Bc * Nc + 255) / 256, 256>>>();
    count_kernel<<<(Bc * Ec) / 256, 256>>>(ei);
    scan_kernel<<<1, 1024>>>();
    scatter_kernel<<<(Bc * Ec) / 256, 256>>>(ei);

    const int SMEM = (8 * Nc + Nc + 256) * (int)sizeof(float);  // 74752 B
    cudaFuncSetAttribute(attn_kernel, cudaFuncAttributeMaxDynamicSharedMemorySize, SMEM);
    attn_kernel<<<Bc * Nc, 256, SMEM>>>(adj, shifts, widths, selfw, out);
}

// round 5
// speedup vs baseline: 1.6917x; 1.6917x over previous
#include <cuda_runtime.h>
#include <math.h>

#define Bc   2
#define Nc   2048
#define Hc   8
#define DHc  32
#define Ec   65536
#define DIN  256
#define Oc   256
#define TQ   16
#define KT   512

// ---------------- scratch globals (no allocation allowed) ----------------
__device__ float g_Q [Bc*Hc*Nc*DHc];   // [b][h][n][d]
__device__ float g_Kt[Bc*Hc*DHc*Nc];   // [b][h][d][n]  (transposed K)
__device__ float g_V [Bc*Hc*Nc*DHc];   // [b][h][n][d]
__device__ float g_ea[(long)Bc*Ec*Hc]; // ffn(ffn(edge_attr)) [b][e][h]
__device__ int   g_cnt   [Bc*Nc];
__device__ int   g_rowptr[Bc*Nc+1];
__device__ int   g_fill  [Bc*Nc];
__device__ int   g_colv  [Bc*Ec];
__device__ float g_eav_t [(long)Hc*Bc*Ec];  // [h][pos] transposed for coalesced per-head reads

// ---------------- K1: QKV projection GEMM -------------------------------
__global__ void qkv_kernel(const float* __restrict__ x,
                           const float* __restrict__ w,
                           const float* __restrict__ bias) {
    __shared__ __align__(16) float As[16][64];   // [k][m]
    __shared__ __align__(16) float Bs[16][64];   // [k][c]
    int tx = threadIdx.x, ty = threadIdx.y;      // 16x16
    int tid = ty * 16 + tx;
    int mb = blockIdx.y * 64, cb = blockIdx.x * 64;

    float acc[4][4];
#pragma unroll
    for (int i = 0; i < 4; i++)
#pragma unroll
        for (int j = 0; j < 4; j++) acc[i][j] = 0.f;

    for (int kb = 0; kb < DIN; kb += 16) {
        {   // load x tile (transposed store)
            int m = tid >> 2, k4 = (tid & 3) * 4;
            float4 f = *(const float4*)&x[(long)(mb + m) * DIN + kb + k4];
            As[k4 + 0][m] = f.x; As[k4 + 1][m] = f.y;
            As[k4 + 2][m] = f.z; As[k4 + 3][m] = f.w;
        }
        {   // load w tile
            int k = tid >> 4, c4 = (tid & 15) * 4;
            *(float4*)&Bs[k][c4] = *(const float4*)&w[(long)(kb + k) * 768 + cb + c4];
        }
        __syncthreads();
#pragma unroll
        for (int kk = 0; kk < 16; kk++) {
            float4 ra = *(const float4*)&As[kk][ty * 4];
            float4 rb = *(const float4*)&Bs[kk][tx * 4];
            float a[4] = {ra.x, ra.y, ra.z, ra.w};
            float b4[4] = {rb.x, rb.y, rb.z, rb.w};
#pragma unroll
            for (int i = 0; i < 4; i++)
#pragma unroll
                for (int j = 0; j < 4; j++) acc[i][j] += a[i] * b4[j];
        }
        __syncthreads();
    }
#pragma unroll
    for (int i = 0; i < 4; i++) {
        int m = mb + ty * 4 + i;
        int b = m >> 11, n = m & (Nc - 1);
#pragma unroll
        for (int j = 0; j < 4; j++) {
            int cc = cb + tx * 4 + j;
            int sel = cc / Oc, r = cc % Oc;
            int h = r / DHc, d = r % DHc;
            float val = acc[i][j] + bias[cc];
            if (sel == 0)      g_Q [((b*Hc + h)*Nc + n)*DHc + d] = val;
            else if (sel == 1) g_Kt[((b*Hc + h)*DHc + d)*Nc + n] = val;
            else               g_V [((b*Hc + h)*Nc + n)*DHc + d] = val;
        }
    }
}

// ---------------- K2: edge FFN (applied twice) ---------------------------
__global__ void edge_ffn_kernel(const float* __restrict__ ea,
                                const float* __restrict__ w1, const float* __restrict__ b1,
                                const float* __restrict__ w2, const float* __restrict__ b2) {
    __shared__ float sw1[64], sw2[64], sb1[8], sb2[8];
    int t = threadIdx.x;
    if (t < 64) { sw1[t] = w1[t]; sw2[t] = w2[t]; }
    if (t < 8)  { sb1[t] = b1[t]; sb2[t] = b2[t]; }
    __syncthreads();

    long idx = (long)blockIdx.x * 256 + t;   // over B*E
    float v[8], u[8];
    const float4* p = (const float4*)(ea + idx * 8);
    float4 f0 = p[0], f1 = p[1];
    v[0]=f0.x; v[1]=f0.y; v[2]=f0.z; v[3]=f0.w;
    v[4]=f1.x; v[5]=f1.y; v[6]=f1.z; v[7]=f1.w;

#pragma unroll
    for (int rep = 0; rep < 2; rep++) {
#pragma unroll
        for (int j = 0; j < 8; j++) {
            float a = sb1[j];
#pragma unroll
            for (int i = 0; i < 8; i++) a += v[i] * sw1[i * 8 + j];
            u[j] = fmaxf(a, 0.f);
        }
#pragma unroll
        for (int j = 0; j < 8; j++) {
            float a = sb2[j];
#pragma unroll
            for (int i = 0; i < 8; i++) a += u[i] * sw2[i * 8 + j];
            v[j] = a;
        }
    }
    float4 o0 = {v[0], v[1], v[2], v[3]}, o1 = {v[4], v[5], v[6], v[7]};
    float4* q = (float4*)(g_ea + idx * 8);
    q[0] = o0; q[1] = o1;
}

// ---------------- K3: CSR build ------------------------------------------
__global__ void zero_cnt_kernel() {
    int i = blockIdx.x * 256 + threadIdx.x;
    if (i < Bc * Nc) g_cnt[i] = 0;
}
__global__ void count_kernel(const int* __restrict__ ei) {
    int idx = blockIdx.x * 256 + threadIdx.x;   // over B*E
    int b = idx / Ec, e = idx - b * Ec;
    int u = ei[(long)b * 2 * Ec + e];
    atomicAdd(&g_cnt[b * Nc + u], 1);
}
__global__ void scan_kernel() {
    __shared__ int part[1024];
    int t = threadIdx.x;
    int l0 = g_cnt[t*4], l1 = g_cnt[t*4+1], l2 = g_cnt[t*4+2], l3 = g_cnt[t*4+3];
    int sum = l0 + l1 + l2 + l3;
    part[t] = sum;
    __syncthreads();
    for (int off = 1; off < 1024; off <<= 1) {
        int v = (t >= off) ? part[t - off] : 0;
        __syncthreads();
        part[t] += v;
        __syncthreads();
    }
    int run = part[t] - sum;   // exclusive base
    g_rowptr[t*4]   = run; g_fill[t*4]   = run; run += l0;
    g_rowptr[t*4+1] = run; g_fill[t*4+1] = run; run += l1;
    g_rowptr[t*4+2] = run; g_fill[t*4+2] = run; run += l2;
    g_rowptr[t*4+3] = run; g_fill[t*4+3] = run; run += l3;
    if (t == 1023) g_rowptr[Bc * Nc] = run;
}
__global__ void scatter_kernel(const int* __restrict__ ei) {
    int idx = blockIdx.x * 256 + threadIdx.x;   // over B*E
    int b = idx / Ec, e = idx - b * Ec;
    int u = ei[(long)b * 2 * Ec + e];
    int v = ei[(long)b * 2 * Ec + Ec + e];
    int pos = atomicAdd(&g_fill[b * Nc + u], 1);
    g_colv[pos] = v;
    const float* src = g_ea + (long)idx * 8;
#pragma unroll
    for (int hh = 0; hh < 8; hh++)
        g_eav_t[(long)hh * (Bc * Ec) + pos] = src[hh];
}

// ---------------- K4: attention, one block per (b, h, q-tile of 16) ------
__global__ void __launch_bounds__(512) attn_kernel(
        const float* __restrict__ adj,
        const float* __restrict__ shifts, const float* __restrict__ widths,
        const float* __restrict__ selfw, float* __restrict__ out) {
    extern __shared__ __align__(16) float sm[];
    float* s   = sm;                     // TQ * Nc           = 32768 floats
    float* Ks  = sm + TQ * Nc;           // 32 * KT           = 16384 floats (K tile / V tile)
    float* qsT = Ks + 32 * KT;           // 32 * TQ           = 512
    float* po  = qsT + 32 * TQ;          // 4 * TQ * 32       = 2048
    float* ls  = po + 4 * TQ * 32;       // TQ

    int tid = threadIdx.x, lane = tid & 31, w = tid >> 5;  // 16 warps
    int qt = blockIdx.x, h = blockIdx.y, b = blockIdx.z;
    int q0 = qt * TQ;

    // load Q tile, transposed [d][qi]
    { int qi = tid >> 5, d = tid & 31;
      qsT[d * TQ + qi] = g_Q[((long)((b*Hc + h)*Nc + q0 + qi))*DHc + d]; }

    float sh = shifts[h], wd = widths[h], sw = selfw[h];
    float inv2w2 = 1.0f / (2.0f * wd * wd);
    const float LOGMIN   = -13.815510557964274f;   // log(1e-6)
    const float INVSCALE = 0.17677669529663687f;   // 1/sqrt(32)

    // ---------- QK^T + moire + self loop ----------
    int qg = w >> 2, kt = w & 3;   // warp: 4 q-rows (qg), 128-k slice (kt)
    const float4* Kt4g = (const float4*)(g_Kt + (long)((b*Hc + h)*DHc) * Nc);

    for (int ks = 0; ks < Nc / KT; ks++) {
        __syncthreads();
        // stage K tile [32][KT]
        for (int i = tid; i < 32 * KT / 4; i += 512) {
            int d = i >> 7, c = i & 127;
            ((float4*)Ks)[d * (KT/4) + c] = Kt4g[(long)d * (Nc/4) + ks * (KT/4) + c];
        }
        __syncthreads();

        float acc[4][4];
#pragma unroll
        for (int i = 0; i < 4; i++)
#pragma unroll
            for (int j = 0; j < 4; j++) acc[i][j] = 0.f;

#pragma unroll
        for (int d = 0; d < 32; d++) {
            float4 qv = *(const float4*)&qsT[d * TQ + qg * 4];
            float4 kv = *(const float4*)&Ks[d * KT + kt * 128 + lane * 4];
            float qa[4] = {qv.x, qv.y, qv.z, qv.w};
            float ka[4] = {kv.x, kv.y, kv.z, kv.w};
#pragma unroll
            for (int i = 0; i < 4; i++)
#pragma unroll
                for (int j = 0; j < 4; j++) acc[i][j] += qa[i] * ka[j];
        }

        int kloc = ks * KT + kt * 128 + lane * 4;
#pragma unroll
        for (int qi = 0; qi < 4; qi++) {
            int row = qg * 4 + qi, q = q0 + row;
            float4 a4 = *(const float4*)&adj[((long)(b*Nc + q))*Nc + kloc];
            float4 r;
            { float dd = a4.x - sh; r.x = acc[qi][0]*INVSCALE + fmaxf(-dd*dd*inv2w2, LOGMIN); }
            { float dd = a4.y - sh; r.y = acc[qi][1]*INVSCALE + fmaxf(-dd*dd*inv2w2, LOGMIN); }
            { float dd = a4.z - sh; r.z = acc[qi][2]*INVSCALE + fmaxf(-dd*dd*inv2w2, LOGMIN); }
            { float dd = a4.w - sh; r.w = acc[qi][3]*INVSCALE + fmaxf(-dd*dd*inv2w2, LOGMIN); }
            if (q >= kloc && q < kloc + 4) ((float*)&r)[q - kloc] += sw;
            *(float4*)&s[(long)row * Nc + kloc] = r;
        }
    }
    __syncthreads();

    // ---------- edge bias (warp w owns row w; unique (u,v) -> race free) ----------
    {
        int q = q0 + w, bq = b * Nc + q;
        int r0 = g_rowptr[bq], r1 = g_rowptr[bq + 1];
        const float* eavh = g_eav_t + (long)h * (Bc * Ec);
        float* srow = s + (long)w * Nc;
        for (int idx = r0 + lane; idx < r1; idx += 32)
            srow[g_colv[idx]] += eavh[idx];
    }
    __syncwarp();

    // ---------- softmax (warp w owns row w) ----------
    {
        float* srow = s + (long)w * Nc;
        float m = -1e30f;
        for (int j = 0; j < 16; j++) {
            float4 v4 = *(const float4*)&srow[j * 128 + lane * 4];
            m = fmaxf(m, fmaxf(fmaxf(v4.x, v4.y), fmaxf(v4.z, v4.w)));
        }
#pragma unroll
        for (int o = 16; o; o >>= 1) m = fmaxf(m, __shfl_xor_sync(~0u, m, o));
        float l = 0.f;
        for (int j = 0; j < 16; j++) {
            float4 v4 = *(const float4*)&srow[j * 128 + lane * 4];
            v4.x = __expf(v4.x - m); v4.y = __expf(v4.y - m);
            v4.z = __expf(v4.z - m); v4.w = __expf(v4.w - m);
            l += v4.x + v4.y + v4.z + v4.w;
            *(float4*)&srow[j * 128 + lane * 4] = v4;
        }
#pragma unroll
        for (int o = 16; o; o >>= 1) l += __shfl_xor_sync(~0u, l, o);
        if (lane == 0) ls[w] = l;
    }

    // ---------- P @ V (warp: 4 q-rows (rq), 128-k slice (kq); lane = d) ----------
    int rq = w >> 2, kq = w & 3;
    float accv[4] = {0.f, 0.f, 0.f, 0.f};
    for (int ks = 0; ks < Nc / KT; ks++) {
        __syncthreads();   // covers softmax writes + prior Ks consumers
        const float4* Vg = (const float4*)(g_V + ((long)((b*Hc + h)*Nc) + ks*KT) * DHc);
        for (int i = tid; i < KT * DHc / 4; i += 512)
            ((float4*)Ks)[i] = Vg[i];     // Vs[k][d], contiguous
        __syncthreads();

        int kbase = kq * 128;
        for (int kk = 0; kk < 128; kk += 4) {
            float v0 = Ks[(kbase + kk + 0) * 32 + lane];
            float v1 = Ks[(kbase + kk + 1) * 32 + lane];
            float v2 = Ks[(kbase + kk + 2) * 32 + lane];
            float v3 = Ks[(kbase + kk + 3) * 32 + lane];
#pragma unroll
            for (int qi = 0; qi < 4; qi++) {
                float4 p = *(const float4*)&s[(long)(rq*4 + qi) * Nc + ks*KT + kbase + kk];
                accv[qi] += p.x * v0 + p.y * v1 + p.z * v2 + p.w * v3;
            }
        }
    }
#pragma unroll
    for (int qi = 0; qi < 4; qi++)
        po[(kq * TQ + rq * 4 + qi) * 32 + lane] = accv[qi];
    __syncthreads();

    // ---------- combine partials + write ----------
    {
        int row = tid >> 5, d = tid & 31;
        float v = po[(0 * TQ + row) * 32 + d] + po[(1 * TQ + row) * 32 + d]
                + po[(2 * TQ + row) * 32 + d] + po[(3 * TQ + row) * 32 + d];
        out[((long)(b * Nc + q0 + row)) * Oc + h * DHc + d] = v / ls[row];
    }
}

// ---------------- launch --------------------------------------------------
extern "C" void kernel_launch(void* const* d_in, const int* in_sizes, int n_in,
                              void* d_out, int out_size) {
    const float* x        = (const float*)d_in[0];
    const float* adj      = (const float*)d_in[1];
    const float* edge_attr= (const float*)d_in[2];
    const float* qkv_w    = (const float*)d_in[3];
    const float* qkv_b    = (const float*)d_in[4];
    const float* e_w1     = (const float*)d_in[5];
    const float* e_b1     = (const float*)d_in[6];
    const float* e_w2     = (const float*)d_in[7];
    const float* e_b2     = (const float*)d_in[8];
    const float* shifts   = (const float*)d_in[9];
    const float* widths   = (const float*)d_in[10];
    const float* selfw    = (const float*)d_in[11];
    const int*   ei       = (const int*)d_in[12];
    float* out = (float*)d_out;

    qkv_kernel<<<dim3(12, 64), dim3(16, 16)>>>(x, qkv_w, qkv_b);
    edge_ffn_kernel<<<(Bc * Ec) / 256, 256>>>(edge_attr, e_w1, e_b1, e_w2, e_b2);
    zero_cnt_kernel<<<(Bc * Nc + 255) / 256, 256>>>();
    count_kernel<<<(Bc * Ec) / 256, 256>>>(ei);
    scan_kernel<<<1, 1024>>>();
    scatter_kernel<<<(Bc * Ec) / 256, 256>>>(ei);

    const int SMEM = (TQ*Nc + 32*KT + 32*TQ + 4*TQ*32 + TQ) * (int)sizeof(float); // 206912 B
    static int smem_set = 0;
    if (!smem_set) {
        cudaFuncSetAttribute(attn_kernel, cudaFuncAttributeMaxDynamicSharedMemorySize, SMEM);
        smem_set = 1;
    }
    attn_kernel<<<dim3(Nc / TQ, Hc, Bc), 512, SMEM>>>(adj, shifts, widths, selfw, out);
}

// round 7
// speedup vs baseline: 2.5540x; 1.5097x over previous
#include <cuda_runtime.h>
#include <math.h>
#include <stdint.h>

#define Bc   2
#define Nc   2048
#define Hc   8
#define DHc  32
#define Ec   65536
#define DIN  256
#define Oc   256
#define TQ   16
#define SP   2052   // s row pitch (floats): 2048+4 -> conflict-free strided LDS
#define QP   36     // q tile pitch

// ---------------- scratch globals (no allocation allowed) ----------------
__device__ float g_Q [Bc*Hc*Nc*DHc];   // [b][h][n][d]
__device__ float g_Kt[Bc*Hc*DHc*Nc];   // [b][h][d][n]  (transposed K)
__device__ float g_V [Bc*Hc*Nc*DHc];   // [b][h][n][d]
__device__ float g_ea[(long)Bc*Ec*Hc]; // ffn(ffn(edge_attr)) [b][e][h]
__device__ int   g_cnt   [Bc*Nc];
__device__ int   g_rowptr[Bc*Nc+1];
__device__ int   g_fill  [Bc*Nc];
__device__ int   g_colv  [Bc*Ec];
__device__ float g_eav_t [(long)Hc*Bc*Ec];  // [h][pos] for coalesced per-head reads

// ---------------- tf32 helpers -------------------------------------------
__device__ __forceinline__ void tf32split(float x, uint32_t& hi, uint32_t& lo) {
    asm("cvt.rna.tf32.f32 %0, %1;" : "=r"(hi) : "f"(x));
    float r = x - __uint_as_float(hi);
    asm("cvt.rna.tf32.f32 %0, %1;" : "=r"(lo) : "f"(r));
}
__device__ __forceinline__ void mma8(float& c0, float& c1, float& c2, float& c3,
                                     uint32_t a0, uint32_t a1, uint32_t a2, uint32_t a3,
                                     uint32_t b0, uint32_t b1) {
    asm("mma.sync.aligned.m16n8k8.row.col.f32.tf32.tf32.f32 "
        "{%0,%1,%2,%3},{%4,%5,%6,%7},{%8,%9},{%0,%1,%2,%3};"
        : "+f"(c0), "+f"(c1), "+f"(c2), "+f"(c3)
        : "r"(a0), "r"(a1), "r"(a2), "r"(a3), "r"(b0), "r"(b1));
}

// ---------------- K1: QKV projection GEMM -------------------------------
__global__ void qkv_kernel(const float* __restrict__ x,
                           const float* __restrict__ w,
                           const float* __restrict__ bias) {
    __shared__ __align__(16) float As[16][64];   // [k][m]
    __shared__ __align__(16) float Bs[16][64];   // [k][c]
    int tx = threadIdx.x, ty = threadIdx.y;      // 16x16
    int tid = ty * 16 + tx;
    int mb = blockIdx.y * 64, cb = blockIdx.x * 64;

    float acc[4][4];
#pragma unroll
    for (int i = 0; i < 4; i++)
#pragma unroll
        for (int j = 0; j < 4; j++) acc[i][j] = 0.f;

    for (int kb = 0; kb < DIN; kb += 16) {
        {   // load x tile (transposed store)
            int m = tid >> 2, k4 = (tid & 3) * 4;
            float4 f = *(const float4*)&x[(long)(mb + m) * DIN + kb + k4];
            As[k4 + 0][m] = f.x; As[k4 + 1][m] = f.y;
            As[k4 + 2][m] = f.z; As[k4 + 3][m] = f.w;
        }
        {   // load w tile
            int k = tid >> 4, c4 = (tid & 15) * 4;
            *(float4*)&Bs[k][c4] = *(const float4*)&w[(long)(kb + k) * 768 + cb + c4];
        }
        __syncthreads();
#pragma unroll
        for (int kk = 0; kk < 16; kk++) {
            float4 ra = *(const float4*)&As[kk][ty * 4];
            float4 rb = *(const float4*)&Bs[kk][tx * 4];
            float a[4] = {ra.x, ra.y, ra.z, ra.w};
            float b4[4] = {rb.x, rb.y, rb.z, rb.w};
#pragma unroll
            for (int i = 0; i < 4; i++)
#pragma unroll
                for (int j = 0; j < 4; j++) acc[i][j] += a[i] * b4[j];
        }
        __syncthreads();
    }
#pragma unroll
    for (int i = 0; i < 4; i++) {
        int m = mb + ty * 4 + i;
        int b = m >> 11, n = m & (Nc - 1);
#pragma unroll
        for (int j = 0; j < 4; j++) {
            int cc = cb + tx * 4 + j;
            int sel = cc / Oc, r = cc % Oc;
            int h = r / DHc, d = r % DHc;
            float val = acc[i][j] + bias[cc];
            if (sel == 0)      g_Q [((b*Hc + h)*Nc + n)*DHc + d] = val;
            else if (sel == 1) g_Kt[((b*Hc + h)*DHc + d)*Nc + n] = val;
            else               g_V [((b*Hc + h)*Nc + n)*DHc + d] = val;
        }
    }
}

// ---------------- K2: edge FFN (applied twice) ---------------------------
__global__ void edge_ffn_kernel(const float* __restrict__ ea,
                                const float* __restrict__ w1, const float* __restrict__ b1,
                                const float* __restrict__ w2, const float* __restrict__ b2) {
    __shared__ float sw1[64], sw2[64], sb1[8], sb2[8];
    int t = threadIdx.x;
    if (t < 64) { sw1[t] = w1[t]; sw2[t] = w2[t]; }
    if (t < 8)  { sb1[t] = b1[t]; sb2[t] = b2[t]; }
    __syncthreads();

    long idx = (long)blockIdx.x * 256 + t;   // over B*E
    float v[8], u[8];
    const float4* p = (const float4*)(ea + idx * 8);
    float4 f0 = p[0], f1 = p[1];
    v[0]=f0.x; v[1]=f0.y; v[2]=f0.z; v[3]=f0.w;
    v[4]=f1.x; v[5]=f1.y; v[6]=f1.z; v[7]=f1.w;

#pragma unroll
    for (int rep = 0; rep < 2; rep++) {
#pragma unroll
        for (int j = 0; j < 8; j++) {
            float a = sb1[j];
#pragma unroll
            for (int i = 0; i < 8; i++) a += v[i] * sw1[i * 8 + j];
            u[j] = fmaxf(a, 0.f);
        }
#pragma unroll
        for (int j = 0; j < 8; j++) {
            float a = sb2[j];
#pragma unroll
            for (int i = 0; i < 8; i++) a += u[i] * sw2[i * 8 + j];
            v[j] = a;
        }
    }
    float4 o0 = {v[0], v[1], v[2], v[3]}, o1 = {v[4], v[5], v[6], v[7]};
    float4* q = (float4*)(g_ea + idx * 8);
    q[0] = o0; q[1] = o1;
}

// ---------------- K3: CSR build ------------------------------------------
__global__ void zero_cnt_kernel() {
    int i = blockIdx.x * 256 + threadIdx.x;
    if (i < Bc * Nc) g_cnt[i] = 0;
}
__global__ void count_kernel(const int* __restrict__ ei) {
    int idx = blockIdx.x * 256 + threadIdx.x;   // over B*E
    int b = idx / Ec, e = idx - b * Ec;
    int u = ei[(long)b * 2 * Ec + e];
    atomicAdd(&g_cnt[b * Nc + u], 1);
}
__global__ void scan_kernel() {
    __shared__ int part[1024];
    int t = threadIdx.x;
    int l0 = g_cnt[t*4], l1 = g_cnt[t*4+1], l2 = g_cnt[t*4+2], l3 = g_cnt[t*4+3];
    int sum = l0 + l1 + l2 + l3;
    part[t] = sum;
    __syncthreads();
    for (int off = 1; off < 1024; off <<= 1) {
        int v = (t >= off) ? part[t - off] : 0;
        __syncthreads();
        part[t] += v;
        __syncthreads();
    }
    int run = part[t] - sum;   // exclusive base
    g_rowptr[t*4]   = run; g_fill[t*4]   = run; run += l0;
    g_rowptr[t*4+1] = run; g_fill[t*4+1] = run; run += l1;
    g_rowptr[t*4+2] = run; g_fill[t*4+2] = run; run += l2;
    g_rowptr[t*4+3] = run; g_fill[t*4+3] = run; run += l3;
    if (t == 1023) g_rowptr[Bc * Nc] = run;
}
__global__ void scatter_kernel(const int* __restrict__ ei) {
    int idx = blockIdx.x * 256 + threadIdx.x;   // over B*E
    int b = idx / Ec, e = idx - b * Ec;
    int u = ei[(long)b * 2 * Ec + e];
    int v = ei[(long)b * 2 * Ec + Ec + e];
    int pos = atomicAdd(&g_fill[b * Nc + u], 1);
    g_colv[pos] = v;
    const float* src = g_ea + (long)idx * 8;
#pragma unroll
    for (int hh = 0; hh < 8; hh++)
        g_eav_t[(long)hh * (Bc * Ec) + pos] = src[hh];
}

// ---------------- K4: attention, mma.sync tf32x3 -------------------------
// block = (qtile of 16, h, b); 16 warps.
// QK: warps partition 2048 keys (128 cols each). PV: warps partition k (128 each).
__global__ void __launch_bounds__(512) attn_kernel(
        const float* __restrict__ adj,
        const float* __restrict__ shifts, const float* __restrict__ widths,
        const float* __restrict__ selfw, float* __restrict__ out) {
    extern __shared__ __align__(16) float sm[];
    float* s   = sm;                     // TQ * SP
    float* qhi = sm + TQ * SP;           // TQ * QP
    float* qlo = qhi + TQ * QP;          // TQ * QP
    float* po  = qlo + TQ * QP;          // 16 * TQ * 32 = 8192
    float* ls  = po + 16 * TQ * 32;      // TQ

    int tid = threadIdx.x, lane = tid & 31, w = tid >> 5;
    int g = lane >> 2, t = lane & 3;
    int qt = blockIdx.x, h = blockIdx.y, b = blockIdx.z;
    int q0 = qt * TQ;

    // ---- stage Q tile, tf32-split ----
    {
        int row = tid >> 5, d = tid & 31;
        float qv = g_Q[((long)((b*Hc + h)*Nc + q0 + row))*DHc + d];
        uint32_t hi, lo; tf32split(qv, hi, lo);
        qhi[row*QP + d] = __uint_as_float(hi);
        qlo[row*QP + d] = __uint_as_float(lo);
    }
    __syncthreads();

    // hoisted A fragments (all 4 k-steps)
    uint32_t qah[4][4], qal[4][4];
#pragma unroll
    for (int ks = 0; ks < 4; ks++) {
        int c0 = ks*8 + t;
        qah[ks][0] = __float_as_uint(qhi[g*QP + c0]);
        qah[ks][1] = __float_as_uint(qhi[(g+8)*QP + c0]);
        qah[ks][2] = __float_as_uint(qhi[g*QP + c0 + 4]);
        qah[ks][3] = __float_as_uint(qhi[(g+8)*QP + c0 + 4]);
        qal[ks][0] = __float_as_uint(qlo[g*QP + c0]);
        qal[ks][1] = __float_as_uint(qlo[(g+8)*QP + c0]);
        qal[ks][2] = __float_as_uint(qlo[g*QP + c0 + 4]);
        qal[ks][3] = __float_as_uint(qlo[(g+8)*QP + c0 + 4]);
    }

    const float INVSCALE = 0.17677669529663687f;   // 1/sqrt(32)
    const float LOGMIN   = -13.815510557964274f;   // log(1e-6)

    // ---- QK^T: warp w owns cols [w*128, w*128+128) ----
    {
        const float* Ktb = g_Kt + (long)((b*Hc + h)*DHc) * Nc;
        for (int nt = 0; nt < 16; nt++) {
            int col0 = w*128 + nt*8;
            float c0 = 0.f, c1 = 0.f, c2 = 0.f, c3 = 0.f;
#pragma unroll
            for (int ks = 0; ks < 4; ks++) {
                float b0f = Ktb[(long)(ks*8 + t)*Nc + col0 + g];
                float b1f = Ktb[(long)(ks*8 + t + 4)*Nc + col0 + g];
                uint32_t b0h, b0l, b1h, b1l;
                tf32split(b0f, b0h, b0l);
                tf32split(b1f, b1h, b1l);
                mma8(c0,c1,c2,c3, qah[ks][0],qah[ks][1],qah[ks][2],qah[ks][3], b0h, b1h);
                mma8(c0,c1,c2,c3, qal[ks][0],qal[ks][1],qal[ks][2],qal[ks][3], b0h, b1h);
                mma8(c0,c1,c2,c3, qah[ks][0],qah[ks][1],qah[ks][2],qah[ks][3], b0l, b1l);
            }
            int cc = col0 + 2*t;
            s[g*SP + cc]     = c0 * INVSCALE;
            s[g*SP + cc + 1] = c1 * INVSCALE;
            s[(g+8)*SP + cc]     = c2 * INVSCALE;
            s[(g+8)*SP + cc + 1] = c3 * INVSCALE;
        }
    }
    __syncthreads();

    // ---- edge bias (warp w owns row w; unique (u,v) -> race free) ----
    {
        int q = q0 + w, bq = b * Nc + q;
        int r0 = g_rowptr[bq], r1 = g_rowptr[bq + 1];
        const float* eavh = g_eav_t + (long)h * (Bc * Ec);
        float* srow = s + (long)w * SP;
        for (int idx = r0 + lane; idx < r1; idx += 32)
            srow[g_colv[idx]] += eavh[idx];
    }
    __syncwarp();

    // ---- moire + self-loop + softmax (warp w owns row w) ----
    {
        int q = q0 + w;
        float sh = shifts[h], wd = widths[h], sw = selfw[h];
        float inv2w2 = 1.0f / (2.0f * wd * wd);
        float* srow = s + (long)w * SP;
        const float* arow = adj + (long)(b*Nc + q) * Nc;

        float m = -1e30f;
        for (int j = 0; j < 16; j++) {
            int idx = j * 128 + lane * 4;
            float4 v4 = *(const float4*)&srow[idx];
            float4 a4 = *(const float4*)&arow[idx];
            { float dd = a4.x - sh; v4.x += fmaxf(-dd*dd*inv2w2, LOGMIN); }
            { float dd = a4.y - sh; v4.y += fmaxf(-dd*dd*inv2w2, LOGMIN); }
            { float dd = a4.z - sh; v4.z += fmaxf(-dd*dd*inv2w2, LOGMIN); }
            { float dd = a4.w - sh; v4.w += fmaxf(-dd*dd*inv2w2, LOGMIN); }
            if (q >= idx && q < idx + 4) ((float*)&v4)[q - idx] += sw;
            *(float4*)&srow[idx] = v4;
            m = fmaxf(m, fmaxf(fmaxf(v4.x, v4.y), fmaxf(v4.z, v4.w)));
        }
#pragma unroll
        for (int o = 16; o; o >>= 1) m = fmaxf(m, __shfl_xor_sync(~0u, m, o));
        float l = 0.f;
        for (int j = 0; j < 16; j++) {
            int idx = j * 128 + lane * 4;
            float4 v4 = *(const float4*)&srow[idx];
            v4.x = __expf(v4.x - m); v4.y = __expf(v4.y - m);
            v4.z = __expf(v4.z - m); v4.w = __expf(v4.w - m);
            l += v4.x + v4.y + v4.z + v4.w;
            *(float4*)&srow[idx] = v4;
        }
#pragma unroll
        for (int o = 16; o; o >>= 1) l += __shfl_xor_sync(~0u, l, o);
        if (lane == 0) ls[w] = l;
    }
    __syncthreads();

    // ---- P @ V: warp w owns k-range [w*128, w*128+128) ----
    {
        const float* Vb = g_V + (long)((b*Hc + h)*Nc) * DHc;
        float acc[4][4];
#pragma unroll
        for (int i = 0; i < 4; i++)
#pragma unroll
            for (int j = 0; j < 4; j++) acc[i][j] = 0.f;

        for (int ks = 0; ks < 16; ks++) {
            int kk = w*128 + ks*8;
            float a0f = s[g*SP + kk + t];
            float a1f = s[(g+8)*SP + kk + t];
            float a2f = s[g*SP + kk + t + 4];
            float a3f = s[(g+8)*SP + kk + t + 4];
            uint32_t a0h,a0l,a1h,a1l,a2h,a2l,a3h,a3l;
            tf32split(a0f, a0h, a0l); tf32split(a1f, a1h, a1l);
            tf32split(a2f, a2h, a2l); tf32split(a3f, a3h, a3l);
#pragma unroll
            for (int nt = 0; nt < 4; nt++) {
                float b0f = Vb[(long)(kk + t)*DHc + nt*8 + g];
                float b1f = Vb[(long)(kk + t + 4)*DHc + nt*8 + g];
                uint32_t b0h, b0l, b1h, b1l;
                tf32split(b0f, b0h, b0l);
                tf32split(b1f, b1h, b1l);
                mma8(acc[nt][0],acc[nt][1],acc[nt][2],acc[nt][3], a0h,a1h,a2h,a3h, b0h, b1h);
                mma8(acc[nt][0],acc[nt][1],acc[nt][2],acc[nt][3], a0l,a1l,a2l,a3l, b0h, b1h);
                mma8(acc[nt][0],acc[nt][1],acc[nt][2],acc[nt][3], a0h,a1h,a2h,a3h, b0l, b1l);
            }
        }
        // partials to smem
#pragma unroll
        for (int nt = 0; nt < 4; nt++) {
            int cc = nt*8 + 2*t;
            po[w*512 + g*32 + cc]         = acc[nt][0];
            po[w*512 + g*32 + cc + 1]     = acc[nt][1];
            po[w*512 + (g+8)*32 + cc]     = acc[nt][2];
            po[w*512 + (g+8)*32 + cc + 1] = acc[nt][3];
        }
    }
    __syncthreads();

    // ---- combine partials + write ----
    {
        int row = tid >> 5, d = tid & 31;
        float v = 0.f;
#pragma unroll
        for (int ww = 0; ww < 16; ww++) v += po[ww*512 + row*32 + d];
        out[((long)(b * Nc + q0 + row)) * Oc + h * DHc + d] = v / ls[row];
    }
}

// ---------------- launch --------------------------------------------------
extern "C" void kernel_launch(void* const* d_in, const int* in_sizes, int n_in,
                              void* d_out, int out_size) {
    const float* x        = (const float*)d_in[0];
    const float* adj      = (const float*)d_in[1];
    const float* edge_attr= (const float*)d_in[2];
    const float* qkv_w    = (const float*)d_in[3];
    const float* qkv_b    = (const float*)d_in[4];
    const float* e_w1     = (const float*)d_in[5];
    const float* e_b1     = (const float*)d_in[6];
    const float* e_w2     = (const float*)d_in[7];
    const float* e_b2     = (const float*)d_in[8];
    const float* shifts   = (const float*)d_in[9];
    const float* widths   = (const float*)d_in[10];
    const float* selfw    = (const float*)d_in[11];
    const int*   ei       = (const int*)d_in[12];
    float* out = (float*)d_out;

    qkv_kernel<<<dim3(12, 64), dim3(16, 16)>>>(x, qkv_w, qkv_b);
    edge_ffn_kernel<<<(Bc * Ec) / 256, 256>>>(edge_attr, e_w1, e_b1, e_w2, e_b2);
    zero_cnt_kernel<<<(Bc * Nc + 255) / 256, 256>>>();
    count_kernel<<<(Bc * Ec) / 256, 256>>>(ei);
    scan_kernel<<<1, 1024>>>();
    scatter_kernel<<<(Bc * Ec) / 256, 256>>>(ei);

    const int SMEM = (TQ*SP + 2*TQ*QP + 16*TQ*32 + TQ) * (int)sizeof(float); // 168768 B
    cudaFuncSetAttribute(attn_kernel, cudaFuncAttributeMaxDynamicSharedMemorySize, SMEM);
    attn_kernel<<<dim3(Nc / TQ, Hc, Bc), 512, SMEM>>>(adj, shifts, widths, selfw, out);
}